// round 1
// baseline (speedup 1.0000x reference)
#include <cuda_runtime.h>
#include <cuda_bf16.h>

// Problem constants
constexpr int B   = 4;
constexpr int S   = 2048;
constexpr int HID = 512;
constexpr int NH  = 8;
constexpr int DH  = 64;          // HID / NH
constexpr int M   = B * S;       // 8192 rows for the projection GEMMs

// Scratch (device globals — no runtime allocation allowed)
__device__ float g_Q[M * HID];
__device__ float g_K[M * HID];
__device__ float g_V[M * HID];
__device__ float g_O[M * HID];

// ---------------------------------------------------------------------------
// GEMM-NT:  C[M,HID] = A[M,HID] @ W[HID,HID]^T   (C[m,n] = sum_k A[m,k]*W[n,k])
// 64x64 block tile, 16-deep k tiles, 4x4 micro-tile per thread, 256 threads.
// Shared tiles stored k-major with pad 68 (16B-aligned, conflict-light).
// ---------------------------------------------------------------------------
__global__ __launch_bounds__(256) void gemm_nt_kernel(
    const float* __restrict__ A, const float* __restrict__ W,
    float* __restrict__ C) {
  __shared__ float As[16][68];   // [k][m]
  __shared__ float Ws[16][68];   // [k][n]

  const int n0 = blockIdx.x * 64;
  const int m0 = blockIdx.y * 64;
  const int t  = threadIdx.x;
  const int tx = t & 15;         // n micro-tile
  const int ty = t >> 4;         // m micro-tile
  const int lrow = t >> 2;       // 0..63 (tile row for loads)
  const int lc   = t & 3;        // 0..3  (k group of 4)

  const float* Arow = A + (size_t)(m0 + lrow) * HID + lc * 4;
  const float* Wrow = W + (size_t)(n0 + lrow) * HID + lc * 4;

  float acc[4][4] = {};

  for (int k0 = 0; k0 < HID; k0 += 16) {
    float4 av = *(const float4*)(Arow + k0);
    float4 wv = *(const float4*)(Wrow + k0);
    __syncthreads();
    As[lc * 4 + 0][lrow] = av.x;
    As[lc * 4 + 1][lrow] = av.y;
    As[lc * 4 + 2][lrow] = av.z;
    As[lc * 4 + 3][lrow] = av.w;
    Ws[lc * 4 + 0][lrow] = wv.x;
    Ws[lc * 4 + 1][lrow] = wv.y;
    Ws[lc * 4 + 2][lrow] = wv.z;
    Ws[lc * 4 + 3][lrow] = wv.w;
    __syncthreads();

#pragma unroll
    for (int kk = 0; kk < 16; kk++) {
      float4 a = *(const float4*)&As[kk][ty * 4];
      float4 b = *(const float4*)&Ws[kk][tx * 4];
      acc[0][0] += a.x * b.x; acc[0][1] += a.x * b.y;
      acc[0][2] += a.x * b.z; acc[0][3] += a.x * b.w;
      acc[1][0] += a.y * b.x; acc[1][1] += a.y * b.y;
      acc[1][2] += a.y * b.z; acc[1][3] += a.y * b.w;
      acc[2][0] += a.z * b.x; acc[2][1] += a.z * b.y;
      acc[2][2] += a.z * b.z; acc[2][3] += a.z * b.w;
      acc[3][0] += a.w * b.x; acc[3][1] += a.w * b.y;
      acc[3][2] += a.w * b.z; acc[3][3] += a.w * b.w;
    }
  }

#pragma unroll
  for (int i = 0; i < 4; i++) {
    float4 r = make_float4(acc[i][0], acc[i][1], acc[i][2], acc[i][3]);
    *(float4*)&C[(size_t)(m0 + ty * 4 + i) * HID + n0 + tx * 4] = r;
  }
}

// ---------------------------------------------------------------------------
// Flash-attention (fp32, online softmax).
// Grid: (S/64, NH, B). Block: 256 threads, 4x4 micro-tiles.
// Q/K/V layouts are the projection outputs: elem (b,s,h,d) at
//   ((b*S + s)*NH + h)*DH + d
// Only keys < valid_len[b] are attended (reference's -1e6 mask underflows to
// exactly 0 weight in fp32, so clipping the kv loop + -1e30 mask is exact).
// ---------------------------------------------------------------------------
constexpr int PAD = 68;
constexpr int ATTN_SMEM = 4 * 64 * PAD * 4;   // Qs, Ks, Vs, Ps

__global__ __launch_bounds__(256) void attn_kernel(
    const float* __restrict__ Q, const float* __restrict__ Km,
    const float* __restrict__ Vm, const int* __restrict__ valid_lens,
    float* __restrict__ O) {
  extern __shared__ float sm[];
  float* Qs = sm;                // [d][m] transposed, 64x68
  float* Ks = Qs + 64 * PAD;     // [d][n] transposed
  float* Vs = Ks + 64 * PAD;     // [n][d] natural
  float* Ps = Vs + 64 * PAD;     // [n][m] transposed probabilities

  const int qt = blockIdx.x, h = blockIdx.y, b = blockIdx.z;
  const int t  = threadIdx.x;
  const int tx = t & 15, ty = t >> 4;
  const int vlen = valid_lens[b];

  // Load Q tile (64 queries x 64 dims), transposed into Qs[d][m]
#pragma unroll
  for (int i = 0; i < 4; i++) {
    int f = t + i * 256;         // float4 slot 0..1023
    int row = f >> 4;            // 0..63
    int cg  = f & 15;            // 0..15
    size_t gidx = ((size_t)(b * S + qt * 64 + row) * NH + h) * DH + cg * 4;
    float4 v = *(const float4*)&Q[gidx];
    Qs[(cg * 4 + 0) * PAD + row] = v.x;
    Qs[(cg * 4 + 1) * PAD + row] = v.y;
    Qs[(cg * 4 + 2) * PAD + row] = v.z;
    Qs[(cg * 4 + 3) * PAD + row] = v.w;
  }

  float m_run[4], l_run[4], acc[4][4];
#pragma unroll
  for (int i = 0; i < 4; i++) {
    m_run[i] = -1e30f;
    l_run[i] = 0.f;
#pragma unroll
    for (int j = 0; j < 4; j++) acc[i][j] = 0.f;
  }

  const int ntiles = (vlen + 63) >> 6;
  for (int kt = 0; kt < ntiles; kt++) {
    const int kbase = kt * 64;
    __syncthreads();   // previous iteration's PV reads done; also fences Qs stores
#pragma unroll
    for (int i = 0; i < 4; i++) {
      int f = t + i * 256;
      int row = f >> 4;
      int cg  = f & 15;
      size_t gidx = ((size_t)(b * S + kbase + row) * NH + h) * DH + cg * 4;
      float4 kv = *(const float4*)&Km[gidx];
      float4 vv = *(const float4*)&Vm[gidx];
      Ks[(cg * 4 + 0) * PAD + row] = kv.x;
      Ks[(cg * 4 + 1) * PAD + row] = kv.y;
      Ks[(cg * 4 + 2) * PAD + row] = kv.z;
      Ks[(cg * 4 + 3) * PAD + row] = kv.w;
      *(float4*)&Vs[row * PAD + cg * 4] = vv;
    }
    __syncthreads();

    // Scores: sc[i][j] = (1/8) * sum_d Q[qrow_i][d] * K[kcol_j][d]
    float sc[4][4] = {};
#pragma unroll
    for (int d = 0; d < 64; d++) {
      float4 a  = *(const float4*)&Qs[d * PAD + ty * 4];
      float4 bb = *(const float4*)&Ks[d * PAD + tx * 4];
      sc[0][0] += a.x * bb.x; sc[0][1] += a.x * bb.y;
      sc[0][2] += a.x * bb.z; sc[0][3] += a.x * bb.w;
      sc[1][0] += a.y * bb.x; sc[1][1] += a.y * bb.y;
      sc[1][2] += a.y * bb.z; sc[1][3] += a.y * bb.w;
      sc[2][0] += a.z * bb.x; sc[2][1] += a.z * bb.y;
      sc[2][2] += a.z * bb.z; sc[2][3] += a.z * bb.w;
      sc[3][0] += a.w * bb.x; sc[3][1] += a.w * bb.y;
      sc[3][2] += a.w * bb.z; sc[3][3] += a.w * bb.w;
    }
#pragma unroll
    for (int i = 0; i < 4; i++)
#pragma unroll
      for (int j = 0; j < 4; j++) {
        sc[i][j] *= 0.125f;                      // 1/sqrt(DH)
        if (kbase + tx * 4 + j >= vlen) sc[i][j] = -1e30f;
      }

    // Online softmax: each query row is owned by 16 consecutive lanes (fixed ty)
#pragma unroll
    for (int i = 0; i < 4; i++) {
      float rm = fmaxf(fmaxf(sc[i][0], sc[i][1]), fmaxf(sc[i][2], sc[i][3]));
#pragma unroll
      for (int off = 8; off > 0; off >>= 1)
        rm = fmaxf(rm, __shfl_xor_sync(0xffffffffu, rm, off));
      float mnew = fmaxf(m_run[i], rm);
      float corr = __expf(m_run[i] - mnew);
      float rs = 0.f;
#pragma unroll
      for (int j = 0; j < 4; j++) {
        float p = __expf(sc[i][j] - mnew);
        Ps[(tx * 4 + j) * PAD + ty * 4 + i] = p;
        rs += p;
      }
#pragma unroll
      for (int off = 8; off > 0; off >>= 1)
        rs += __shfl_xor_sync(0xffffffffu, rs, off);
      l_run[i] = l_run[i] * corr + rs;
      m_run[i] = mnew;
#pragma unroll
      for (int j = 0; j < 4; j++) acc[i][j] *= corr;
    }
    __syncthreads();

    // acc += P @ V  (thread owns 4 q-rows x 4 d-cols)
#pragma unroll 8
    for (int n = 0; n < 64; n++) {
      float4 a = *(const float4*)&Ps[n * PAD + ty * 4];
      float4 v = *(const float4*)&Vs[n * PAD + tx * 4];
      acc[0][0] += a.x * v.x; acc[0][1] += a.x * v.y;
      acc[0][2] += a.x * v.z; acc[0][3] += a.x * v.w;
      acc[1][0] += a.y * v.x; acc[1][1] += a.y * v.y;
      acc[1][2] += a.y * v.z; acc[1][3] += a.y * v.w;
      acc[2][0] += a.z * v.x; acc[2][1] += a.z * v.y;
      acc[2][2] += a.z * v.z; acc[2][3] += a.z * v.w;
      acc[3][0] += a.w * v.x; acc[3][1] += a.w * v.y;
      acc[3][2] += a.w * v.z; acc[3][3] += a.w * v.w;
    }
  }

  // Normalize and store in (B, S, NH*DH) layout so out-proj is a plain GEMM.
#pragma unroll
  for (int i = 0; i < 4; i++) {
    float inv = 1.f / l_run[i];
    float4 r = make_float4(acc[i][0] * inv, acc[i][1] * inv,
                           acc[i][2] * inv, acc[i][3] * inv);
    size_t gidx = ((size_t)(b * S + qt * 64 + ty * 4 + i) * NH + h) * DH + tx * 4;
    *(float4*)&O[gidx] = r;
  }
}

// ---------------------------------------------------------------------------
extern "C" void kernel_launch(void* const* d_in, const int* in_sizes, int n_in,
                              void* d_out, int out_size) {
  const float* queries = (const float*)d_in[0];
  const float* keys    = (const float*)d_in[1];
  const float* values  = (const float*)d_in[2];
  const int*   vlens   = (const int*)d_in[3];
  const float* Wq      = (const float*)d_in[4];
  const float* Wk      = (const float*)d_in[5];
  const float* Wv      = (const float*)d_in[6];
  const float* Wo      = (const float*)d_in[7];
  float* out = (float*)d_out;

  float *gq, *gk, *gv, *go;
  cudaGetSymbolAddress((void**)&gq, g_Q);
  cudaGetSymbolAddress((void**)&gk, g_K);
  cudaGetSymbolAddress((void**)&gv, g_V);
  cudaGetSymbolAddress((void**)&go, g_O);

  dim3 gemm_grid(HID / 64, M / 64);   // (8, 128)
  gemm_nt_kernel<<<gemm_grid, 256>>>(queries, Wq, gq);
  gemm_nt_kernel<<<gemm_grid, 256>>>(keys,    Wk, gk);
  gemm_nt_kernel<<<gemm_grid, 256>>>(values,  Wv, gv);

  cudaFuncSetAttribute(attn_kernel, cudaFuncAttributeMaxDynamicSharedMemorySize,
                       ATTN_SMEM);
  attn_kernel<<<dim3(S / 64, NH, B), 256, ATTN_SMEM>>>(gq, gk, gv, vlens, go);

  gemm_nt_kernel<<<gemm_grid, 256>>>(go, Wo, out);
}

// round 3
// speedup vs baseline: 1.3499x; 1.3499x over previous
#include <cuda_runtime.h>
#include <cuda_bf16.h>
#include <cstdint>

// Problem constants
constexpr int B   = 4;
constexpr int S   = 2048;
constexpr int HID = 512;
constexpr int NH  = 8;
constexpr int DH  = 64;
constexpr int M   = B * S;       // 8192

// Scratch (device globals — no runtime allocation allowed)
__device__ float g_Q[M * HID];
__device__ float g_K[M * HID];
__device__ float g_V[M * HID];
__device__ float g_O[M * HID];
__device__ __nv_bfloat16 g_ah[M * HID];
__device__ __nv_bfloat16 g_al[M * HID];
__device__ __nv_bfloat16 g_wh[HID * HID];
__device__ __nv_bfloat16 g_wl[HID * HID];

// ---------------------------------------------------------------------------
// mma.sync / ldmatrix helpers (plain sm_80+ PTX — no 103a feature gating)
// ---------------------------------------------------------------------------
__device__ __forceinline__ uint32_t smem_u32(const void* p) {
  uint32_t a;
  asm("{ .reg .u64 t; cvta.to.shared.u64 t, %1; cvt.u32.u64 %0, t; }"
      : "=r"(a) : "l"(p));
  return a;
}

#define LDMX4(r0, r1, r2, r3, addr)                                       \
  asm volatile(                                                           \
      "ldmatrix.sync.aligned.m8n8.x4.shared.b16 {%0,%1,%2,%3}, [%4];"     \
      : "=r"(r0), "=r"(r1), "=r"(r2), "=r"(r3) : "r"(addr))

__device__ __forceinline__ void mma_bf16(float& c0, float& c1, float& c2,
                                         float& c3, uint32_t a0, uint32_t a1,
                                         uint32_t a2, uint32_t a3,
                                         uint32_t b0, uint32_t b1) {
  asm volatile(
      "mma.sync.aligned.m16n8k16.row.col.f32.bf16.bf16.f32 "
      "{%0,%1,%2,%3}, {%4,%5,%6,%7}, {%8,%9}, {%0,%1,%2,%3};"
      : "+f"(c0), "+f"(c1), "+f"(c2), "+f"(c3)
      : "r"(a0), "r"(a1), "r"(a2), "r"(a3), "r"(b0), "r"(b1));
}

// ---------------------------------------------------------------------------
// fp32 -> (bf16 hi, bf16 lo) split. n4 = number of float4 elements.
// ---------------------------------------------------------------------------
__global__ __launch_bounds__(256) void split_kernel(
    const float* __restrict__ x, __nv_bfloat16* __restrict__ hi,
    __nv_bfloat16* __restrict__ lo, int n4) {
  int i = blockIdx.x * blockDim.x + threadIdx.x;
  if (i >= n4) return;
  float4 v = ((const float4*)x)[i];
  __nv_bfloat16 h0 = __float2bfloat16(v.x);
  __nv_bfloat16 h1 = __float2bfloat16(v.y);
  __nv_bfloat16 h2 = __float2bfloat16(v.z);
  __nv_bfloat16 h3 = __float2bfloat16(v.w);
  __nv_bfloat16 l0 = __float2bfloat16(v.x - __bfloat162float(h0));
  __nv_bfloat16 l1 = __float2bfloat16(v.y - __bfloat162float(h1));
  __nv_bfloat16 l2 = __float2bfloat16(v.z - __bfloat162float(h2));
  __nv_bfloat16 l3 = __float2bfloat16(v.w - __bfloat162float(h3));
  uint2 ho, lw;
  ho.x = (uint32_t)__bfloat16_as_ushort(h0) |
         ((uint32_t)__bfloat16_as_ushort(h1) << 16);
  ho.y = (uint32_t)__bfloat16_as_ushort(h2) |
         ((uint32_t)__bfloat16_as_ushort(h3) << 16);
  lw.x = (uint32_t)__bfloat16_as_ushort(l0) |
         ((uint32_t)__bfloat16_as_ushort(l1) << 16);
  lw.y = (uint32_t)__bfloat16_as_ushort(l2) |
         ((uint32_t)__bfloat16_as_ushort(l3) << 16);
  ((uint2*)hi)[i] = ho;
  ((uint2*)lo)[i] = lw;
}

// ---------------------------------------------------------------------------
// HMMA bf16x3 GEMM-NT: C[M,512] = A @ W^T with fp32-equivalent accuracy.
// CTA tile 128(M) x 128(N); 8 warps, warp tile 64x32 (4x4 m16n8k16 tiles).
// K staged in smem in chunks of 64 (row stride 144B -> ldmatrix conflict-free).
// D = Ah*Wh + Ah*Wl + Al*Wh  (fp32 accumulate in registers).
// ---------------------------------------------------------------------------
constexpr int RS = 72;                    // smem row stride in bf16 (144 B)
constexpr int TILE_BYTES = 128 * RS * 2;  // 18432 per tile
constexpr int SA_H = 0;
constexpr int SA_L = SA_H + TILE_BYTES;
constexpr int SW_H = SA_L + TILE_BYTES;
constexpr int SW_L = SW_H + TILE_BYTES;
constexpr int GEMM_SMEM = SW_L + TILE_BYTES;  // 73728 B

__global__ __launch_bounds__(256) void gemm_tc_hmma(
    const __nv_bfloat16* __restrict__ Ah, const __nv_bfloat16* __restrict__ Al,
    const __nv_bfloat16* __restrict__ Wh, const __nv_bfloat16* __restrict__ Wl,
    float* __restrict__ C) {
  extern __shared__ __align__(128) char smem[];
  const uint32_t sb = smem_u32(smem);
  const int t = threadIdx.x;
  const int wid = t >> 5, l = t & 31;
  const int wm = wid >> 2;     // 0..1  (M half)
  const int wn = wid & 3;      // 0..3  (N quarter)
  const int m0 = blockIdx.y * 128;
  const int n0 = blockIdx.x * 128;

  float acc[4][4][4] = {};     // [mt][nt][c0..c3]

  // Per-lane ldmatrix source rows (within tile) and 16B k-offsets
  const int a_row = (l & 15);             // + mt*16 + wm*64
  const int a_koff = ((l >> 4) & 1) * 16; // bytes
  const int b_row = (l & 7) + ((l >> 4) & 1) * 8;  // + ntpair*16 + wn*32
  const int b_koff = ((l >> 3) & 1) * 16;

  for (int kc = 0; kc < 8; kc++) {
    const int koff = kc * 64;
    __syncthreads();
    // --- cooperative load: 128 rows x 64 bf16 per tile (1024 uint4 each) ---
#pragma unroll
    for (int i = 0; i < 4; i++) {
      int v = t + i * 256;
      int row = v >> 3, c = v & 7;
      size_t ga = (size_t)(m0 + row) * HID + koff + c * 8;
      size_t gw = (size_t)(n0 + row) * HID + koff + c * 8;
      uint32_t so = row * (RS * 2) + c * 16;
      *(uint4*)(smem + SA_H + so) = *(const uint4*)(Ah + ga);
      *(uint4*)(smem + SA_L + so) = *(const uint4*)(Al + ga);
      *(uint4*)(smem + SW_H + so) = *(const uint4*)(Wh + gw);
      *(uint4*)(smem + SW_L + so) = *(const uint4*)(Wl + gw);
    }
    __syncthreads();

#pragma unroll
    for (int ks = 0; ks < 4; ks++) {      // 4 x k16 per chunk
      const int kb = ks * 32;             // byte offset of k16 block
      uint32_t ah[4][4], al[4][4], bh[8], bl[8];
#pragma unroll
      for (int mt = 0; mt < 4; mt++) {
        uint32_t ra = (wm * 64 + mt * 16 + a_row) * (RS * 2) + kb + a_koff;
        LDMX4(ah[mt][0], ah[mt][1], ah[mt][2], ah[mt][3], sb + SA_H + ra);
        LDMX4(al[mt][0], al[mt][1], al[mt][2], al[mt][3], sb + SA_L + ra);
      }
#pragma unroll
      for (int np = 0; np < 2; np++) {    // each x4 covers 2 n-tiles
        uint32_t rb = (wn * 32 + np * 16 + b_row) * (RS * 2) + kb + b_koff;
        LDMX4(bh[np * 4 + 0], bh[np * 4 + 1], bh[np * 4 + 2], bh[np * 4 + 3],
              sb + SW_H + rb);
        LDMX4(bl[np * 4 + 0], bl[np * 4 + 1], bl[np * 4 + 2], bl[np * 4 + 3],
              sb + SW_L + rb);
      }
#pragma unroll
      for (int mt = 0; mt < 4; mt++)
#pragma unroll
        for (int nt = 0; nt < 4; nt++) {
          float* c = acc[mt][nt];
          mma_bf16(c[0], c[1], c[2], c[3], ah[mt][0], ah[mt][1], ah[mt][2],
                   ah[mt][3], bh[nt * 2], bh[nt * 2 + 1]);
          mma_bf16(c[0], c[1], c[2], c[3], ah[mt][0], ah[mt][1], ah[mt][2],
                   ah[mt][3], bl[nt * 2], bl[nt * 2 + 1]);
          mma_bf16(c[0], c[1], c[2], c[3], al[mt][0], al[mt][1], al[mt][2],
                   al[mt][3], bh[nt * 2], bh[nt * 2 + 1]);
        }
    }
  }

  // --- epilogue: acc layout c0,c1 -> row (l>>2), cols (l&3)*2; c2,c3 -> +8 ---
  const int er = l >> 2, ec = (l & 3) * 2;
#pragma unroll
  for (int mt = 0; mt < 4; mt++) {
    int row = m0 + wm * 64 + mt * 16 + er;
#pragma unroll
    for (int nt = 0; nt < 4; nt++) {
      int col = n0 + wn * 32 + nt * 8 + ec;
      *(float2*)&C[(size_t)row * HID + col] =
          make_float2(acc[mt][nt][0], acc[mt][nt][1]);
      *(float2*)&C[(size_t)(row + 8) * HID + col] =
          make_float2(acc[mt][nt][2], acc[mt][nt][3]);
    }
  }
}

// ---------------------------------------------------------------------------
// Flash-attention (fp32, online softmax) — unchanged (known good).
// ---------------------------------------------------------------------------
constexpr int PAD = 68;
constexpr int ATTN_SMEM = 4 * 64 * PAD * 4;

__global__ __launch_bounds__(256) void attn_kernel(
    const float* __restrict__ Q, const float* __restrict__ Km,
    const float* __restrict__ Vm, const int* __restrict__ valid_lens,
    float* __restrict__ O) {
  extern __shared__ float sm[];
  float* Qs = sm;
  float* Ks = Qs + 64 * PAD;
  float* Vs = Ks + 64 * PAD;
  float* Ps = Vs + 64 * PAD;

  const int qt = blockIdx.x, h = blockIdx.y, b = blockIdx.z;
  const int t = threadIdx.x;
  const int tx = t & 15, ty = t >> 4;
  const int vlen = valid_lens[b];

#pragma unroll
  for (int i = 0; i < 4; i++) {
    int f = t + i * 256;
    int row = f >> 4;
    int cg = f & 15;
    size_t gidx = ((size_t)(b * S + qt * 64 + row) * NH + h) * DH + cg * 4;
    float4 v = *(const float4*)&Q[gidx];
    Qs[(cg * 4 + 0) * PAD + row] = v.x;
    Qs[(cg * 4 + 1) * PAD + row] = v.y;
    Qs[(cg * 4 + 2) * PAD + row] = v.z;
    Qs[(cg * 4 + 3) * PAD + row] = v.w;
  }

  float m_run[4], l_run[4], acc[4][4];
#pragma unroll
  for (int i = 0; i < 4; i++) {
    m_run[i] = -1e30f;
    l_run[i] = 0.f;
#pragma unroll
    for (int j = 0; j < 4; j++) acc[i][j] = 0.f;
  }

  const int ntiles = (vlen + 63) >> 6;
  for (int kt = 0; kt < ntiles; kt++) {
    const int kbase = kt * 64;
    __syncthreads();
#pragma unroll
    for (int i = 0; i < 4; i++) {
      int f = t + i * 256;
      int row = f >> 4;
      int cg = f & 15;
      size_t gidx = ((size_t)(b * S + kbase + row) * NH + h) * DH + cg * 4;
      float4 kv = *(const float4*)&Km[gidx];
      float4 vv = *(const float4*)&Vm[gidx];
      Ks[(cg * 4 + 0) * PAD + row] = kv.x;
      Ks[(cg * 4 + 1) * PAD + row] = kv.y;
      Ks[(cg * 4 + 2) * PAD + row] = kv.z;
      Ks[(cg * 4 + 3) * PAD + row] = kv.w;
      *(float4*)&Vs[row * PAD + cg * 4] = vv;
    }
    __syncthreads();

    float sc[4][4] = {};
#pragma unroll
    for (int d = 0; d < 64; d++) {
      float4 a = *(const float4*)&Qs[d * PAD + ty * 4];
      float4 bb = *(const float4*)&Ks[d * PAD + tx * 4];
      sc[0][0] += a.x * bb.x; sc[0][1] += a.x * bb.y;
      sc[0][2] += a.x * bb.z; sc[0][3] += a.x * bb.w;
      sc[1][0] += a.y * bb.x; sc[1][1] += a.y * bb.y;
      sc[1][2] += a.y * bb.z; sc[1][3] += a.y * bb.w;
      sc[2][0] += a.z * bb.x; sc[2][1] += a.z * bb.y;
      sc[2][2] += a.z * bb.z; sc[2][3] += a.z * bb.w;
      sc[3][0] += a.w * bb.x; sc[3][1] += a.w * bb.y;
      sc[3][2] += a.w * bb.z; sc[3][3] += a.w * bb.w;
    }
#pragma unroll
    for (int i = 0; i < 4; i++)
#pragma unroll
      for (int j = 0; j < 4; j++) {
        sc[i][j] *= 0.125f;
        if (kbase + tx * 4 + j >= vlen) sc[i][j] = -1e30f;
      }

#pragma unroll
    for (int i = 0; i < 4; i++) {
      float rm = fmaxf(fmaxf(sc[i][0], sc[i][1]), fmaxf(sc[i][2], sc[i][3]));
#pragma unroll
      for (int off = 8; off > 0; off >>= 1)
        rm = fmaxf(rm, __shfl_xor_sync(0xffffffffu, rm, off));
      float mnew = fmaxf(m_run[i], rm);
      float corr = __expf(m_run[i] - mnew);
      float rs = 0.f;
#pragma unroll
      for (int j = 0; j < 4; j++) {
        float p = __expf(sc[i][j] - mnew);
        Ps[(tx * 4 + j) * PAD + ty * 4 + i] = p;
        rs += p;
      }
#pragma unroll
      for (int off = 8; off > 0; off >>= 1)
        rs += __shfl_xor_sync(0xffffffffu, rs, off);
      l_run[i] = l_run[i] * corr + rs;
      m_run[i] = mnew;
#pragma unroll
      for (int j = 0; j < 4; j++) acc[i][j] *= corr;
    }
    __syncthreads();

#pragma unroll 8
    for (int n = 0; n < 64; n++) {
      float4 a = *(const float4*)&Ps[n * PAD + ty * 4];
      float4 v = *(const float4*)&Vs[n * PAD + tx * 4];
      acc[0][0] += a.x * v.x; acc[0][1] += a.x * v.y;
      acc[0][2] += a.x * v.z; acc[0][3] += a.x * v.w;
      acc[1][0] += a.y * v.x; acc[1][1] += a.y * v.y;
      acc[1][2] += a.y * v.z; acc[1][3] += a.y * v.w;
      acc[2][0] += a.z * v.x; acc[2][1] += a.z * v.y;
      acc[2][2] += a.z * v.z; acc[2][3] += a.z * v.w;
      acc[3][0] += a.w * v.x; acc[3][1] += a.w * v.y;
      acc[3][2] += a.w * v.z; acc[3][3] += a.w * v.w;
    }
  }

#pragma unroll
  for (int i = 0; i < 4; i++) {
    float inv = 1.f / l_run[i];
    float4 r = make_float4(acc[i][0] * inv, acc[i][1] * inv,
                           acc[i][2] * inv, acc[i][3] * inv);
    size_t gidx = ((size_t)(b * S + qt * 64 + ty * 4 + i) * NH + h) * DH + tx * 4;
    *(float4*)&O[gidx] = r;
  }
}

// ---------------------------------------------------------------------------
extern "C" void kernel_launch(void* const* d_in, const int* in_sizes, int n_in,
                              void* d_out, int out_size) {
  const float* queries = (const float*)d_in[0];
  const float* keys    = (const float*)d_in[1];
  const float* values  = (const float*)d_in[2];
  const int*   vlens   = (const int*)d_in[3];
  const float* Wq      = (const float*)d_in[4];
  const float* Wk      = (const float*)d_in[5];
  const float* Wv      = (const float*)d_in[6];
  const float* Wo      = (const float*)d_in[7];
  float* out = (float*)d_out;

  float *gq, *gk, *gv, *go;
  cudaGetSymbolAddress((void**)&gq, g_Q);
  cudaGetSymbolAddress((void**)&gk, g_K);
  cudaGetSymbolAddress((void**)&gv, g_V);
  cudaGetSymbolAddress((void**)&go, g_O);
  __nv_bfloat16 *ah, *al, *wh, *wl;
  cudaGetSymbolAddress((void**)&ah, g_ah);
  cudaGetSymbolAddress((void**)&al, g_al);
  cudaGetSymbolAddress((void**)&wh, g_wh);
  cudaGetSymbolAddress((void**)&wl, g_wl);

  cudaFuncSetAttribute(gemm_tc_hmma,
                       cudaFuncAttributeMaxDynamicSharedMemorySize, GEMM_SMEM);
  cudaFuncSetAttribute(attn_kernel,
                       cudaFuncAttributeMaxDynamicSharedMemorySize, ATTN_SMEM);

  const int act_n4 = M * HID / 4;    // 1,048,576
  const int w_n4   = HID * HID / 4;  // 65,536
  dim3 gemm_grid(HID / 128, M / 128);  // (4, 64)

  // Q = queries @ Wq^T
  split_kernel<<<act_n4 / 256, 256>>>(queries, ah, al, act_n4);
  split_kernel<<<w_n4 / 256, 256>>>(Wq, wh, wl, w_n4);
  gemm_tc_hmma<<<gemm_grid, 256, GEMM_SMEM>>>(ah, al, wh, wl, gq);
  // K
  split_kernel<<<act_n4 / 256, 256>>>(keys, ah, al, act_n4);
  split_kernel<<<w_n4 / 256, 256>>>(Wk, wh, wl, w_n4);
  gemm_tc_hmma<<<gemm_grid, 256, GEMM_SMEM>>>(ah, al, wh, wl, gk);
  // V
  split_kernel<<<act_n4 / 256, 256>>>(values, ah, al, act_n4);
  split_kernel<<<w_n4 / 256, 256>>>(Wv, wh, wl, w_n4);
  gemm_tc_hmma<<<gemm_grid, 256, GEMM_SMEM>>>(ah, al, wh, wl, gv);

  // attention
  attn_kernel<<<dim3(S / 64, NH, B), 256, ATTN_SMEM>>>(gq, gk, gv, vlens, go);

  // out = O @ Wo^T
  split_kernel<<<act_n4 / 256, 256>>>(go, ah, al, act_n4);
  split_kernel<<<w_n4 / 256, 256>>>(Wo, wh, wl, w_n4);
  gemm_tc_hmma<<<gemm_grid, 256, GEMM_SMEM>>>(ah, al, wh, wl, out);
}

// round 4
// speedup vs baseline: 2.4646x; 1.8257x over previous
#include <cuda_runtime.h>
#include <cuda_bf16.h>
#include <cstdint>

// Problem constants
constexpr int B   = 4;
constexpr int S   = 2048;
constexpr int HID = 512;
constexpr int NH  = 8;
constexpr int DH  = 64;
constexpr int M   = B * S;       // 8192

// Scratch (device globals — no runtime allocation allowed)
__device__ __nv_bfloat16 g_xh[M * HID], g_xl[M * HID];
__device__ __nv_bfloat16 g_wh[HID * HID], g_wl[HID * HID];
__device__ __nv_bfloat16 g_qh[M * HID], g_ql[M * HID];
__device__ __nv_bfloat16 g_kh[M * HID], g_kl[M * HID];
__device__ __nv_bfloat16 g_vh[M * HID], g_vl[M * HID];
__device__ __nv_bfloat16 g_oh[M * HID], g_ol[M * HID];

// ---------------------------------------------------------------------------
// mma.sync / ldmatrix helpers (plain sm_80+ PTX)
// ---------------------------------------------------------------------------
__device__ __forceinline__ uint32_t smem_u32(const void* p) {
  uint32_t a;
  asm("{ .reg .u64 t; cvta.to.shared.u64 t, %1; cvt.u32.u64 %0, t; }"
      : "=r"(a) : "l"(p));
  return a;
}

#define LDMX4(r0, r1, r2, r3, addr)                                       \
  asm volatile(                                                           \
      "ldmatrix.sync.aligned.m8n8.x4.shared.b16 {%0,%1,%2,%3}, [%4];"     \
      : "=r"(r0), "=r"(r1), "=r"(r2), "=r"(r3) : "r"(addr))

__device__ __forceinline__ void mma_bf16(float& c0, float& c1, float& c2,
                                         float& c3, uint32_t a0, uint32_t a1,
                                         uint32_t a2, uint32_t a3,
                                         uint32_t b0, uint32_t b1) {
  asm volatile(
      "mma.sync.aligned.m16n8k16.row.col.f32.bf16.bf16.f32 "
      "{%0,%1,%2,%3}, {%4,%5,%6,%7}, {%8,%9}, {%0,%1,%2,%3};"
      : "+f"(c0), "+f"(c1), "+f"(c2), "+f"(c3)
      : "r"(a0), "r"(a1), "r"(a2), "r"(a3), "r"(b0), "r"(b1));
}

__device__ __forceinline__ uint32_t pack_bf16(float a, float b) {
  __nv_bfloat162 t = __floats2bfloat162_rn(a, b);
  return *(uint32_t*)&t;
}

// ---------------------------------------------------------------------------
// fp32 -> (bf16 hi, bf16 lo) split. n4 = number of float4 elements.
// ---------------------------------------------------------------------------
__global__ __launch_bounds__(256) void split_kernel(
    const float* __restrict__ x, __nv_bfloat16* __restrict__ hi,
    __nv_bfloat16* __restrict__ lo, int n4) {
  int i = blockIdx.x * blockDim.x + threadIdx.x;
  if (i >= n4) return;
  float4 v = ((const float4*)x)[i];
  float hx = __bfloat162float(__float2bfloat16(v.x));
  float hy = __bfloat162float(__float2bfloat16(v.y));
  float hz = __bfloat162float(__float2bfloat16(v.z));
  float hw = __bfloat162float(__float2bfloat16(v.w));
  uint2 ho, lw;
  ho.x = pack_bf16(v.x, v.y);
  ho.y = pack_bf16(v.z, v.w);
  lw.x = pack_bf16(v.x - hx, v.y - hy);
  lw.y = pack_bf16(v.z - hz, v.w - hw);
  ((uint2*)hi)[i] = ho;
  ((uint2*)lo)[i] = lw;
}

// ---------------------------------------------------------------------------
// HMMA bf16x3 GEMM-NT: C[M,512] = A @ W^T with fp32-equivalent accuracy.
// CTA 128x128, 8 warps, warp 64x32 (4x4 m16n8k16). If SPLIT: emit bf16 hi/lo.
// ---------------------------------------------------------------------------
constexpr int RS = 72;                    // smem row stride in bf16 (144 B)
constexpr int TILE_BYTES = 128 * RS * 2;  // 18432 per tile
constexpr int SA_H = 0;
constexpr int SA_L = SA_H + TILE_BYTES;
constexpr int SW_H = SA_L + TILE_BYTES;
constexpr int SW_L = SW_H + TILE_BYTES;
constexpr int GEMM_SMEM = SW_L + TILE_BYTES;  // 73728 B

template <bool SPLIT>
__global__ __launch_bounds__(256) void gemm_tc_hmma(
    const __nv_bfloat16* __restrict__ Ah, const __nv_bfloat16* __restrict__ Al,
    const __nv_bfloat16* __restrict__ Wh, const __nv_bfloat16* __restrict__ Wl,
    float* __restrict__ C, __nv_bfloat16* __restrict__ Ch,
    __nv_bfloat16* __restrict__ Cl) {
  extern __shared__ __align__(128) char smem[];
  const uint32_t sb = smem_u32(smem);
  const int t = threadIdx.x;
  const int wid = t >> 5, l = t & 31;
  const int wm = wid >> 2;
  const int wn = wid & 3;
  const int m0 = blockIdx.y * 128;
  const int n0 = blockIdx.x * 128;

  float acc[4][4][4] = {};

  const int a_row = (l & 15);
  const int a_koff = ((l >> 4) & 1) * 16;
  const int b_row = (l & 7) + ((l >> 4) & 1) * 8;
  const int b_koff = ((l >> 3) & 1) * 16;

  for (int kc = 0; kc < 8; kc++) {
    const int koff = kc * 64;
    __syncthreads();
#pragma unroll
    for (int i = 0; i < 4; i++) {
      int v = t + i * 256;
      int row = v >> 3, c = v & 7;
      size_t ga = (size_t)(m0 + row) * HID + koff + c * 8;
      size_t gw = (size_t)(n0 + row) * HID + koff + c * 8;
      uint32_t so = row * (RS * 2) + c * 16;
      *(uint4*)(smem + SA_H + so) = *(const uint4*)(Ah + ga);
      *(uint4*)(smem + SA_L + so) = *(const uint4*)(Al + ga);
      *(uint4*)(smem + SW_H + so) = *(const uint4*)(Wh + gw);
      *(uint4*)(smem + SW_L + so) = *(const uint4*)(Wl + gw);
    }
    __syncthreads();

#pragma unroll
    for (int ks = 0; ks < 4; ks++) {
      const int kb = ks * 32;
      uint32_t ah[4][4], al[4][4], bh[8], bl[8];
#pragma unroll
      for (int mt = 0; mt < 4; mt++) {
        uint32_t ra = (wm * 64 + mt * 16 + a_row) * (RS * 2) + kb + a_koff;
        LDMX4(ah[mt][0], ah[mt][1], ah[mt][2], ah[mt][3], sb + SA_H + ra);
        LDMX4(al[mt][0], al[mt][1], al[mt][2], al[mt][3], sb + SA_L + ra);
      }
#pragma unroll
      for (int np = 0; np < 2; np++) {
        uint32_t rb = (wn * 32 + np * 16 + b_row) * (RS * 2) + kb + b_koff;
        LDMX4(bh[np * 4 + 0], bh[np * 4 + 1], bh[np * 4 + 2], bh[np * 4 + 3],
              sb + SW_H + rb);
        LDMX4(bl[np * 4 + 0], bl[np * 4 + 1], bl[np * 4 + 2], bl[np * 4 + 3],
              sb + SW_L + rb);
      }
#pragma unroll
      for (int mt = 0; mt < 4; mt++)
#pragma unroll
        for (int nt = 0; nt < 4; nt++) {
          float* c = acc[mt][nt];
          mma_bf16(c[0], c[1], c[2], c[3], ah[mt][0], ah[mt][1], ah[mt][2],
                   ah[mt][3], bh[nt * 2], bh[nt * 2 + 1]);
          mma_bf16(c[0], c[1], c[2], c[3], ah[mt][0], ah[mt][1], ah[mt][2],
                   ah[mt][3], bl[nt * 2], bl[nt * 2 + 1]);
          mma_bf16(c[0], c[1], c[2], c[3], al[mt][0], al[mt][1], al[mt][2],
                   al[mt][3], bh[nt * 2], bh[nt * 2 + 1]);
        }
    }
  }

  const int er = l >> 2, ec = (l & 3) * 2;
#pragma unroll
  for (int mt = 0; mt < 4; mt++) {
    int row = m0 + wm * 64 + mt * 16 + er;
#pragma unroll
    for (int nt = 0; nt < 4; nt++) {
      int col = n0 + wn * 32 + nt * 8 + ec;
      float* a = acc[mt][nt];
      if constexpr (SPLIT) {
        float h0 = __bfloat162float(__float2bfloat16(a[0]));
        float h1 = __bfloat162float(__float2bfloat16(a[1]));
        float h2 = __bfloat162float(__float2bfloat16(a[2]));
        float h3 = __bfloat162float(__float2bfloat16(a[3]));
        size_t i0 = (size_t)row * HID + col;
        size_t i1 = (size_t)(row + 8) * HID + col;
        *(uint32_t*)&Ch[i0] = pack_bf16(a[0], a[1]);
        *(uint32_t*)&Cl[i0] = pack_bf16(a[0] - h0, a[1] - h1);
        *(uint32_t*)&Ch[i1] = pack_bf16(a[2], a[3]);
        *(uint32_t*)&Cl[i1] = pack_bf16(a[2] - h2, a[3] - h3);
      } else {
        *(float2*)&C[(size_t)row * HID + col] = make_float2(a[0], a[1]);
        *(float2*)&C[(size_t)(row + 8) * HID + col] = make_float2(a[2], a[3]);
      }
    }
  }
}

// ---------------------------------------------------------------------------
// HMMA flash attention (bf16x3, fp32 softmax). CTA: 128 q x one (b,h).
// 8 warps x 16 q-rows. kv tiles of 64. V staged transposed in smem so the
// PV B-operand uses the same (verified) non-trans ldmatrix path as the GEMM.
// ---------------------------------------------------------------------------
constexpr int AQ_H = 0;                       // 128 rows
constexpr int AQ_L = AQ_H + 128 * RS * 2;
constexpr int AK_H = AQ_L + 128 * RS * 2;     // 64 rows
constexpr int AK_L = AK_H + 64 * RS * 2;
constexpr int AV_H = AK_L + 64 * RS * 2;      // 64 dh-rows x 64 keys
constexpr int AV_L = AV_H + 64 * RS * 2;
constexpr int ATTN_SMEM = AV_L + 64 * RS * 2; // 73728 B

__global__ __launch_bounds__(256) void attn_hmma(
    const __nv_bfloat16* __restrict__ Qh, const __nv_bfloat16* __restrict__ Ql,
    const __nv_bfloat16* __restrict__ Kh, const __nv_bfloat16* __restrict__ Kl,
    const __nv_bfloat16* __restrict__ Vh, const __nv_bfloat16* __restrict__ Vl,
    const int* __restrict__ valid_lens, __nv_bfloat16* __restrict__ Oh,
    __nv_bfloat16* __restrict__ Ol) {
  extern __shared__ __align__(128) char smem[];
  const uint32_t sb = smem_u32(smem);
  const int qt = blockIdx.x, h = blockIdx.y, b = blockIdx.z;
  const int t = threadIdx.x;
  const int wid = t >> 5, l = t & 31;
  const int q0 = qt * 128;
  const int vlen = valid_lens[b];

  // --- stage Q tile (128 x 64) hi/lo ---
#pragma unroll
  for (int i = 0; i < 4; i++) {
    int v = t + i * 256;
    int row = v >> 3, c = v & 7;
    size_t g = (size_t)(b * S + q0 + row) * HID + h * DH + c * 8;
    uint32_t so = row * (RS * 2) + c * 16;
    *(uint4*)(smem + AQ_H + so) = *(const uint4*)(Qh + g);
    *(uint4*)(smem + AQ_L + so) = *(const uint4*)(Ql + g);
  }
  __syncthreads();

  const int a_row = (l & 15);
  const int a_koff = ((l >> 4) & 1) * 16;
  const int b_row = (l & 7) + ((l >> 4) & 1) * 8;
  const int b_koff = ((l >> 3) & 1) * 16;
  const int cb = (l & 3) * 2;

  // --- Q fragments to registers (live across the whole kv loop) ---
  uint32_t qh[4][4], ql[4][4];
#pragma unroll
  for (int ks = 0; ks < 4; ks++) {
    uint32_t ra = (wid * 16 + a_row) * (RS * 2) + ks * 32 + a_koff;
    LDMX4(qh[ks][0], qh[ks][1], qh[ks][2], qh[ks][3], sb + AQ_H + ra);
    LDMX4(ql[ks][0], ql[ks][1], ql[ks][2], ql[ks][3], sb + AQ_L + ra);
  }

  float oacc[8][4] = {};
  float m0r = -1e30f, m1r = -1e30f, l0r = 0.f, l1r = 0.f;

  const int ntiles = (vlen + 63) >> 6;
  for (int kt = 0; kt < ntiles; kt++) {
    const int kbase = kt * 64;
    __syncthreads();
    // --- stage K (rows=key) and V (transposed: rows=dh) hi/lo ---
#pragma unroll
    for (int i = 0; i < 2; i++) {
      int v = t + i * 256;
      int key = v >> 3, c = v & 7;
      size_t g = (size_t)(b * S + kbase + key) * HID + h * DH + c * 8;
      uint32_t so = key * (RS * 2) + c * 16;
      *(uint4*)(smem + AK_H + so) = *(const uint4*)(Kh + g);
      *(uint4*)(smem + AK_L + so) = *(const uint4*)(Kl + g);
      uint4 hv = *(const uint4*)(Vh + g);
      uint4 lv = *(const uint4*)(Vl + g);
      const __nv_bfloat16* hp = (const __nv_bfloat16*)&hv;
      const __nv_bfloat16* lp = (const __nv_bfloat16*)&lv;
#pragma unroll
      for (int j = 0; j < 8; j++) {
        uint32_t vo = (c * 8 + j) * (RS * 2) + key * 2;
        *(__nv_bfloat16*)(smem + AV_H + vo) = hp[j];
        *(__nv_bfloat16*)(smem + AV_L + vo) = lp[j];
      }
    }
    __syncthreads();

    // --- scores = Q K^T (bf16x3), 16 q-rows x 64 keys per warp ---
    float sc[8][4];
#pragma unroll
    for (int nt = 0; nt < 8; nt++)
#pragma unroll
      for (int c = 0; c < 4; c++) sc[nt][c] = 0.f;
#pragma unroll
    for (int ks = 0; ks < 4; ks++) {
      uint32_t khf[16], klf[16];
#pragma unroll
      for (int np = 0; np < 4; np++) {
        uint32_t rb = (np * 16 + b_row) * (RS * 2) + ks * 32 + b_koff;
        LDMX4(khf[np * 4 + 0], khf[np * 4 + 1], khf[np * 4 + 2],
              khf[np * 4 + 3], sb + AK_H + rb);
        LDMX4(klf[np * 4 + 0], klf[np * 4 + 1], klf[np * 4 + 2],
              klf[np * 4 + 3], sb + AK_L + rb);
      }
#pragma unroll
      for (int nt = 0; nt < 8; nt++) {
        float* c = sc[nt];
        mma_bf16(c[0], c[1], c[2], c[3], qh[ks][0], qh[ks][1], qh[ks][2],
                 qh[ks][3], khf[nt * 2], khf[nt * 2 + 1]);
        mma_bf16(c[0], c[1], c[2], c[3], qh[ks][0], qh[ks][1], qh[ks][2],
                 qh[ks][3], klf[nt * 2], klf[nt * 2 + 1]);
        mma_bf16(c[0], c[1], c[2], c[3], ql[ks][0], ql[ks][1], ql[ks][2],
                 ql[ks][3], khf[nt * 2], khf[nt * 2 + 1]);
      }
    }

    // --- scale + mask ---
#pragma unroll
    for (int nt = 0; nt < 8; nt++)
#pragma unroll
      for (int c = 0; c < 4; c++) sc[nt][c] *= 0.125f;
    if (kbase + 64 > vlen) {
#pragma unroll
      for (int nt = 0; nt < 8; nt++) {
        int k0 = kbase + nt * 8 + cb;
        if (k0 >= vlen) { sc[nt][0] = -1e30f; sc[nt][2] = -1e30f; }
        if (k0 + 1 >= vlen) { sc[nt][1] = -1e30f; sc[nt][3] = -1e30f; }
      }
    }

    // --- online softmax (rows r0 = l>>2 and r0+8; 4 lanes per row) ---
    float rm0 = -1e30f, rm1 = -1e30f;
#pragma unroll
    for (int nt = 0; nt < 8; nt++) {
      rm0 = fmaxf(rm0, fmaxf(sc[nt][0], sc[nt][1]));
      rm1 = fmaxf(rm1, fmaxf(sc[nt][2], sc[nt][3]));
    }
    rm0 = fmaxf(rm0, __shfl_xor_sync(0xffffffffu, rm0, 1));
    rm0 = fmaxf(rm0, __shfl_xor_sync(0xffffffffu, rm0, 2));
    rm1 = fmaxf(rm1, __shfl_xor_sync(0xffffffffu, rm1, 1));
    rm1 = fmaxf(rm1, __shfl_xor_sync(0xffffffffu, rm1, 2));
    float mn0 = fmaxf(m0r, rm0), mn1 = fmaxf(m1r, rm1);
    float corr0 = __expf(m0r - mn0), corr1 = __expf(m1r - mn1);

    uint32_t ph[8][2], pl[8][2];
    float rs0 = 0.f, rs1 = 0.f;
#pragma unroll
    for (int nt = 0; nt < 8; nt++) {
      float p0 = __expf(sc[nt][0] - mn0);
      float p1 = __expf(sc[nt][1] - mn0);
      float p2 = __expf(sc[nt][2] - mn1);
      float p3 = __expf(sc[nt][3] - mn1);
      rs0 += p0 + p1;
      rs1 += p2 + p3;
      float h0 = __bfloat162float(__float2bfloat16(p0));
      float h1 = __bfloat162float(__float2bfloat16(p1));
      float h2 = __bfloat162float(__float2bfloat16(p2));
      float h3 = __bfloat162float(__float2bfloat16(p3));
      ph[nt][0] = pack_bf16(p0, p1);
      ph[nt][1] = pack_bf16(p2, p3);
      pl[nt][0] = pack_bf16(p0 - h0, p1 - h1);
      pl[nt][1] = pack_bf16(p2 - h2, p3 - h3);
    }
    rs0 += __shfl_xor_sync(0xffffffffu, rs0, 1);
    rs0 += __shfl_xor_sync(0xffffffffu, rs0, 2);
    rs1 += __shfl_xor_sync(0xffffffffu, rs1, 1);
    rs1 += __shfl_xor_sync(0xffffffffu, rs1, 2);
    l0r = l0r * corr0 + rs0;
    l1r = l1r * corr1 + rs1;
    m0r = mn0;
    m1r = mn1;
#pragma unroll
    for (int nt = 0; nt < 8; nt++) {
      oacc[nt][0] *= corr0;
      oacc[nt][1] *= corr0;
      oacc[nt][2] *= corr1;
      oacc[nt][3] *= corr1;
    }

    // --- oacc += P V : A-frags come straight from score fragments ---
#pragma unroll
    for (int ks = 0; ks < 4; ks++) {
      uint32_t vhf[16], vlf[16];
#pragma unroll
      for (int np = 0; np < 4; np++) {
        uint32_t rb = (np * 16 + b_row) * (RS * 2) + ks * 32 + b_koff;
        LDMX4(vhf[np * 4 + 0], vhf[np * 4 + 1], vhf[np * 4 + 2],
              vhf[np * 4 + 3], sb + AV_H + rb);
        LDMX4(vlf[np * 4 + 0], vlf[np * 4 + 1], vlf[np * 4 + 2],
              vlf[np * 4 + 3], sb + AV_L + rb);
      }
      uint32_t a0 = ph[2 * ks][0], a1 = ph[2 * ks][1];
      uint32_t a2 = ph[2 * ks + 1][0], a3 = ph[2 * ks + 1][1];
      uint32_t e0 = pl[2 * ks][0], e1 = pl[2 * ks][1];
      uint32_t e2 = pl[2 * ks + 1][0], e3 = pl[2 * ks + 1][1];
#pragma unroll
      for (int nt = 0; nt < 8; nt++) {
        float* c = oacc[nt];
        mma_bf16(c[0], c[1], c[2], c[3], a0, a1, a2, a3, vhf[nt * 2],
                 vhf[nt * 2 + 1]);
        mma_bf16(c[0], c[1], c[2], c[3], a0, a1, a2, a3, vlf[nt * 2],
                 vlf[nt * 2 + 1]);
        mma_bf16(c[0], c[1], c[2], c[3], e0, e1, e2, e3, vhf[nt * 2],
                 vhf[nt * 2 + 1]);
      }
    }
  }

  // --- epilogue: normalize, split to bf16 hi/lo, store ---
  float inv0 = 1.f / l0r, inv1 = 1.f / l1r;
  int r0 = q0 + wid * 16 + (l >> 2);
#pragma unroll
  for (int nt = 0; nt < 8; nt++) {
    int col = h * DH + nt * 8 + cb;
    float o0 = oacc[nt][0] * inv0, o1 = oacc[nt][1] * inv0;
    float o2 = oacc[nt][2] * inv1, o3 = oacc[nt][3] * inv1;
    float h0 = __bfloat162float(__float2bfloat16(o0));
    float h1 = __bfloat162float(__float2bfloat16(o1));
    float h2 = __bfloat162float(__float2bfloat16(o2));
    float h3 = __bfloat162float(__float2bfloat16(o3));
    size_t i0 = (size_t)(b * S + r0) * HID + col;
    size_t i1 = (size_t)(b * S + r0 + 8) * HID + col;
    *(uint32_t*)&Oh[i0] = pack_bf16(o0, o1);
    *(uint32_t*)&Ol[i0] = pack_bf16(o0 - h0, o1 - h1);
    *(uint32_t*)&Oh[i1] = pack_bf16(o2, o3);
    *(uint32_t*)&Ol[i1] = pack_bf16(o2 - h2, o3 - h3);
  }
}

// ---------------------------------------------------------------------------
extern "C" void kernel_launch(void* const* d_in, const int* in_sizes, int n_in,
                              void* d_out, int out_size) {
  const float* queries = (const float*)d_in[0];
  const float* keys    = (const float*)d_in[1];
  const float* values  = (const float*)d_in[2];
  const int*   vlens   = (const int*)d_in[3];
  const float* Wq      = (const float*)d_in[4];
  const float* Wk      = (const float*)d_in[5];
  const float* Wv      = (const float*)d_in[6];
  const float* Wo      = (const float*)d_in[7];
  float* out = (float*)d_out;

  __nv_bfloat16 *xh, *xl, *wh, *wl, *qh, *ql, *kh, *kl, *vh, *vl, *oh, *ol;
  cudaGetSymbolAddress((void**)&xh, g_xh);
  cudaGetSymbolAddress((void**)&xl, g_xl);
  cudaGetSymbolAddress((void**)&wh, g_wh);
  cudaGetSymbolAddress((void**)&wl, g_wl);
  cudaGetSymbolAddress((void**)&qh, g_qh);
  cudaGetSymbolAddress((void**)&ql, g_ql);
  cudaGetSymbolAddress((void**)&kh, g_kh);
  cudaGetSymbolAddress((void**)&kl, g_kl);
  cudaGetSymbolAddress((void**)&vh, g_vh);
  cudaGetSymbolAddress((void**)&vl, g_vl);
  cudaGetSymbolAddress((void**)&oh, g_oh);
  cudaGetSymbolAddress((void**)&ol, g_ol);

  cudaFuncSetAttribute(gemm_tc_hmma<true>,
                       cudaFuncAttributeMaxDynamicSharedMemorySize, GEMM_SMEM);
  cudaFuncSetAttribute(gemm_tc_hmma<false>,
                       cudaFuncAttributeMaxDynamicSharedMemorySize, GEMM_SMEM);
  cudaFuncSetAttribute(attn_hmma,
                       cudaFuncAttributeMaxDynamicSharedMemorySize, ATTN_SMEM);

  const int act_n4 = M * HID / 4;
  const int w_n4   = HID * HID / 4;
  dim3 gemm_grid(HID / 128, M / 128);  // (4, 64)

  // Q/K/V projections (emit bf16 hi/lo directly)
  split_kernel<<<act_n4 / 256, 256>>>(queries, xh, xl, act_n4);
  split_kernel<<<w_n4 / 256, 256>>>(Wq, wh, wl, w_n4);
  gemm_tc_hmma<true><<<gemm_grid, 256, GEMM_SMEM>>>(xh, xl, wh, wl, nullptr,
                                                    qh, ql);
  split_kernel<<<act_n4 / 256, 256>>>(keys, xh, xl, act_n4);
  split_kernel<<<w_n4 / 256, 256>>>(Wk, wh, wl, w_n4);
  gemm_tc_hmma<true><<<gemm_grid, 256, GEMM_SMEM>>>(xh, xl, wh, wl, nullptr,
                                                    kh, kl);
  split_kernel<<<act_n4 / 256, 256>>>(values, xh, xl, act_n4);
  split_kernel<<<w_n4 / 256, 256>>>(Wv, wh, wl, w_n4);
  gemm_tc_hmma<true><<<gemm_grid, 256, GEMM_SMEM>>>(xh, xl, wh, wl, nullptr,
                                                    vh, vl);

  // attention (reads hi/lo, writes hi/lo)
  attn_hmma<<<dim3(S / 128, NH, B), 256, ATTN_SMEM>>>(qh, ql, kh, kl, vh, vl,
                                                      vlens, oh, ol);

  // output projection (fp32 out)
  split_kernel<<<w_n4 / 256, 256>>>(Wo, wh, wl, w_n4);
  gemm_tc_hmma<false><<<gemm_grid, 256, GEMM_SMEM>>>(oh, ol, wh, wl, out,
                                                     nullptr, nullptr);
}

// round 5
// speedup vs baseline: 3.0841x; 1.2514x over previous
#include <cuda_runtime.h>
#include <cuda_bf16.h>
#include <cstdint>

// Problem constants
constexpr int B   = 4;
constexpr int S   = 2048;
constexpr int HID = 512;
constexpr int NH  = 8;
constexpr int DH  = 64;
constexpr int M   = B * S;       // 8192

// Scratch (device globals — no runtime allocation allowed)
__device__ __nv_bfloat16 g_wh[HID * HID], g_wl[HID * HID];
__device__ __nv_bfloat16 g_qh[M * HID], g_ql[M * HID];
__device__ __nv_bfloat16 g_kh[M * HID], g_kl[M * HID];
__device__ __nv_bfloat16 g_vh[M * HID], g_vl[M * HID];
__device__ __nv_bfloat16 g_oh[M * HID], g_ol[M * HID];

// ---------------------------------------------------------------------------
// mma.sync / ldmatrix / cp.async helpers (plain sm_80+ PTX)
// ---------------------------------------------------------------------------
__device__ __forceinline__ uint32_t smem_u32(const void* p) {
  uint32_t a;
  asm("{ .reg .u64 t; cvta.to.shared.u64 t, %1; cvt.u32.u64 %0, t; }"
      : "=r"(a) : "l"(p));
  return a;
}

#define LDMX4(r0, r1, r2, r3, addr)                                       \
  asm volatile(                                                           \
      "ldmatrix.sync.aligned.m8n8.x4.shared.b16 {%0,%1,%2,%3}, [%4];"     \
      : "=r"(r0), "=r"(r1), "=r"(r2), "=r"(r3) : "r"(addr))

#define LDMX4T(r0, r1, r2, r3, addr)                                      \
  asm volatile(                                                           \
      "ldmatrix.sync.aligned.m8n8.x4.trans.shared.b16 {%0,%1,%2,%3}, [%4];" \
      : "=r"(r0), "=r"(r1), "=r"(r2), "=r"(r3) : "r"(addr))

#define CP_ASYNC16(dst, src)                                              \
  asm volatile("cp.async.cg.shared.global [%0], [%1], 16;" ::             \
                   "r"(dst), "l"(src))
#define CP_COMMIT() asm volatile("cp.async.commit_group;" ::: "memory")
#define CP_WAIT0() asm volatile("cp.async.wait_group 0;" ::: "memory")

__device__ __forceinline__ void mma_bf16(float& c0, float& c1, float& c2,
                                         float& c3, uint32_t a0, uint32_t a1,
                                         uint32_t a2, uint32_t a3,
                                         uint32_t b0, uint32_t b1) {
  asm volatile(
      "mma.sync.aligned.m16n8k16.row.col.f32.bf16.bf16.f32 "
      "{%0,%1,%2,%3}, {%4,%5,%6,%7}, {%8,%9}, {%0,%1,%2,%3};"
      : "+f"(c0), "+f"(c1), "+f"(c2), "+f"(c3)
      : "r"(a0), "r"(a1), "r"(a2), "r"(a3), "r"(b0), "r"(b1));
}

__device__ __forceinline__ uint32_t pack_bf16(float a, float b) {
  __nv_bfloat162 t = __floats2bfloat162_rn(a, b);
  return *(uint32_t*)&t;
}

// ---------------------------------------------------------------------------
// fp32 -> (bf16 hi, bf16 lo) split (weights only now).
// ---------------------------------------------------------------------------
__global__ __launch_bounds__(256) void split_kernel(
    const float* __restrict__ x, __nv_bfloat16* __restrict__ hi,
    __nv_bfloat16* __restrict__ lo, int n4) {
  int i = blockIdx.x * blockDim.x + threadIdx.x;
  if (i >= n4) return;
  float4 v = ((const float4*)x)[i];
  float hx = __bfloat162float(__float2bfloat16(v.x));
  float hy = __bfloat162float(__float2bfloat16(v.y));
  float hz = __bfloat162float(__float2bfloat16(v.z));
  float hw = __bfloat162float(__float2bfloat16(v.w));
  uint2 ho, lw;
  ho.x = pack_bf16(v.x, v.y);
  ho.y = pack_bf16(v.z, v.w);
  lw.x = pack_bf16(v.x - hx, v.y - hy);
  lw.y = pack_bf16(v.z - hz, v.w - hw);
  ((uint2*)hi)[i] = ho;
  ((uint2*)lo)[i] = lw;
}

// ---------------------------------------------------------------------------
// HMMA bf16x3 GEMM-NT: C[M,512] = A @ W^T with fp32-equivalent accuracy.
// CTA 128x128, 8 warps, warp 64x32 (4x4 m16n8k16).
// AFP32: A read as fp32, hi/lo conversion fused into the smem-store path.
// SPLIT: emit bf16 hi/lo instead of fp32.
// ---------------------------------------------------------------------------
constexpr int RS = 72;                    // smem row stride in bf16 (144 B)
constexpr int TILE_BYTES = 128 * RS * 2;  // 18432 per tile
constexpr int SA_H = 0;
constexpr int SA_L = SA_H + TILE_BYTES;
constexpr int SW_H = SA_L + TILE_BYTES;
constexpr int SW_L = SW_H + TILE_BYTES;
constexpr int GEMM_SMEM = SW_L + TILE_BYTES;  // 73728 B

template <bool AFP32, bool SPLIT>
__global__ __launch_bounds__(256) void gemm_tc_hmma(
    const float* __restrict__ Af, const __nv_bfloat16* __restrict__ Ah,
    const __nv_bfloat16* __restrict__ Al, const __nv_bfloat16* __restrict__ Wh,
    const __nv_bfloat16* __restrict__ Wl, float* __restrict__ C,
    __nv_bfloat16* __restrict__ Ch, __nv_bfloat16* __restrict__ Cl) {
  extern __shared__ __align__(128) char smem[];
  const uint32_t sb = smem_u32(smem);
  const int t = threadIdx.x;
  const int wid = t >> 5, l = t & 31;
  const int wm = wid >> 2;
  const int wn = wid & 3;
  const int m0 = blockIdx.y * 128;
  const int n0 = blockIdx.x * 128;

  float acc[4][4][4] = {};

  const int a_row = (l & 15);
  const int a_koff = ((l >> 4) & 1) * 16;
  const int b_row = (l & 7) + ((l >> 4) & 1) * 8;
  const int b_koff = ((l >> 3) & 1) * 16;

  for (int kc = 0; kc < 8; kc++) {
    const int koff = kc * 64;
    __syncthreads();
    // --- A tiles ---
    if constexpr (AFP32) {
#pragma unroll
      for (int i = 0; i < 8; i++) {     // 2048 float4
        int v = t + i * 256;
        int row = v >> 4, c = v & 15;   // 16 float4 per 64-float row
        float4 fv = *(const float4*)(Af + (size_t)(m0 + row) * HID + koff +
                                     c * 4);
        float hx = __bfloat162float(__float2bfloat16(fv.x));
        float hy = __bfloat162float(__float2bfloat16(fv.y));
        float hz = __bfloat162float(__float2bfloat16(fv.z));
        float hw = __bfloat162float(__float2bfloat16(fv.w));
        uint2 ho, lw;
        ho.x = pack_bf16(fv.x, fv.y);
        ho.y = pack_bf16(fv.z, fv.w);
        lw.x = pack_bf16(fv.x - hx, fv.y - hy);
        lw.y = pack_bf16(fv.z - hz, fv.w - hw);
        uint32_t so = row * (RS * 2) + c * 8;
        *(uint2*)(smem + SA_H + so) = ho;
        *(uint2*)(smem + SA_L + so) = lw;
      }
    } else {
#pragma unroll
      for (int i = 0; i < 4; i++) {     // 1024 uint4 per tile
        int v = t + i * 256;
        int row = v >> 3, c = v & 7;
        size_t ga = (size_t)(m0 + row) * HID + koff + c * 8;
        uint32_t so = row * (RS * 2) + c * 16;
        *(uint4*)(smem + SA_H + so) = *(const uint4*)(Ah + ga);
        *(uint4*)(smem + SA_L + so) = *(const uint4*)(Al + ga);
      }
    }
    // --- W tiles ---
#pragma unroll
    for (int i = 0; i < 4; i++) {
      int v = t + i * 256;
      int row = v >> 3, c = v & 7;
      size_t gw = (size_t)(n0 + row) * HID + koff + c * 8;
      uint32_t so = row * (RS * 2) + c * 16;
      *(uint4*)(smem + SW_H + so) = *(const uint4*)(Wh + gw);
      *(uint4*)(smem + SW_L + so) = *(const uint4*)(Wl + gw);
    }
    __syncthreads();

#pragma unroll
    for (int ks = 0; ks < 4; ks++) {
      const int kb = ks * 32;
      uint32_t ah[4][4], al[4][4], bh[8], bl[8];
#pragma unroll
      for (int mt = 0; mt < 4; mt++) {
        uint32_t ra = (wm * 64 + mt * 16 + a_row) * (RS * 2) + kb + a_koff;
        LDMX4(ah[mt][0], ah[mt][1], ah[mt][2], ah[mt][3], sb + SA_H + ra);
        LDMX4(al[mt][0], al[mt][1], al[mt][2], al[mt][3], sb + SA_L + ra);
      }
#pragma unroll
      for (int np = 0; np < 2; np++) {
        uint32_t rb = (wn * 32 + np * 16 + b_row) * (RS * 2) + kb + b_koff;
        LDMX4(bh[np * 4 + 0], bh[np * 4 + 1], bh[np * 4 + 2], bh[np * 4 + 3],
              sb + SW_H + rb);
        LDMX4(bl[np * 4 + 0], bl[np * 4 + 1], bl[np * 4 + 2], bl[np * 4 + 3],
              sb + SW_L + rb);
      }
#pragma unroll
      for (int mt = 0; mt < 4; mt++)
#pragma unroll
        for (int nt = 0; nt < 4; nt++) {
          float* c = acc[mt][nt];
          mma_bf16(c[0], c[1], c[2], c[3], ah[mt][0], ah[mt][1], ah[mt][2],
                   ah[mt][3], bh[nt * 2], bh[nt * 2 + 1]);
          mma_bf16(c[0], c[1], c[2], c[3], ah[mt][0], ah[mt][1], ah[mt][2],
                   ah[mt][3], bl[nt * 2], bl[nt * 2 + 1]);
          mma_bf16(c[0], c[1], c[2], c[3], al[mt][0], al[mt][1], al[mt][2],
                   al[mt][3], bh[nt * 2], bh[nt * 2 + 1]);
        }
    }
  }

  const int er = l >> 2, ec = (l & 3) * 2;
#pragma unroll
  for (int mt = 0; mt < 4; mt++) {
    int row = m0 + wm * 64 + mt * 16 + er;
#pragma unroll
    for (int nt = 0; nt < 4; nt++) {
      int col = n0 + wn * 32 + nt * 8 + ec;
      float* a = acc[mt][nt];
      if constexpr (SPLIT) {
        float h0 = __bfloat162float(__float2bfloat16(a[0]));
        float h1 = __bfloat162float(__float2bfloat16(a[1]));
        float h2 = __bfloat162float(__float2bfloat16(a[2]));
        float h3 = __bfloat162float(__float2bfloat16(a[3]));
        size_t i0 = (size_t)row * HID + col;
        size_t i1 = (size_t)(row + 8) * HID + col;
        *(uint32_t*)&Ch[i0] = pack_bf16(a[0], a[1]);
        *(uint32_t*)&Cl[i0] = pack_bf16(a[0] - h0, a[1] - h1);
        *(uint32_t*)&Ch[i1] = pack_bf16(a[2], a[3]);
        *(uint32_t*)&Cl[i1] = pack_bf16(a[2] - h2, a[3] - h3);
      } else {
        *(float2*)&C[(size_t)row * HID + col] = make_float2(a[0], a[1]);
        *(float2*)&C[(size_t)(row + 8) * HID + col] = make_float2(a[2], a[3]);
      }
    }
  }
}

// ---------------------------------------------------------------------------
// HMMA flash attention (bf16x3, fp32 softmax). CTA: 128 q x one (b,h).
// 8 warps x 16 q-rows, kv tiles of 64.
// K and V both staged row-major (row=key) via 2-stage cp.async pipeline;
// PV B-fragments come from ldmatrix.trans on V (no scalar transpose).
// ---------------------------------------------------------------------------
constexpr int AQ_H = 0;                        // Q hi: 128 x 144B
constexpr int AQ_L = 128 * RS * 2;             // 18432
constexpr int STG0 = 2 * 128 * RS * 2;         // 36864: stage area
constexpr int KV_COMP = 64 * RS * 2;           // 9216 per component
constexpr int STG_SZ = 4 * KV_COMP;            // Kh,Kl,Vh,Vl = 36864
constexpr int ATTN_SMEM = STG0 + 2 * STG_SZ;   // 110592

__global__ __launch_bounds__(256) void attn_hmma(
    const __nv_bfloat16* __restrict__ Qh, const __nv_bfloat16* __restrict__ Ql,
    const __nv_bfloat16* __restrict__ Kh, const __nv_bfloat16* __restrict__ Kl,
    const __nv_bfloat16* __restrict__ Vh, const __nv_bfloat16* __restrict__ Vl,
    const int* __restrict__ valid_lens, __nv_bfloat16* __restrict__ Oh,
    __nv_bfloat16* __restrict__ Ol) {
  extern __shared__ __align__(128) char smem[];
  const uint32_t sb = smem_u32(smem);
  const int qt = blockIdx.x, h = blockIdx.y, b = blockIdx.z;
  const int t = threadIdx.x;
  const int wid = t >> 5, l = t & 31;
  const int q0 = qt * 128;
  const int vlen = valid_lens[b];
  const int ntiles = (vlen + 63) >> 6;

  const __nv_bfloat16* kv_src[4] = {Kh, Kl, Vh, Vl};

  // issue one kv tile (2048 cp.async of 16B across 256 threads)
  auto issue_tile = [&](int stage, int kbase) {
#pragma unroll
    for (int i = 0; i < 8; i++) {
      int idx = t + i * 256;
      int comp = idx >> 9;               // 0..3
      int r = (idx >> 3) & 63;           // key row
      int c = idx & 7;                   // 16B group
      const __nv_bfloat16* src =
          kv_src[comp] + (size_t)(b * S + kbase + r) * HID + h * DH + c * 8;
      uint32_t dst =
          sb + STG0 + stage * STG_SZ + comp * KV_COMP + r * (RS * 2) + c * 16;
      CP_ASYNC16(dst, src);
    }
  };

  // prologue: start tile 0, stage Q with plain stores
  issue_tile(0, 0);
  CP_COMMIT();
#pragma unroll
  for (int i = 0; i < 4; i++) {
    int v = t + i * 256;
    int row = v >> 3, c = v & 7;
    size_t g = (size_t)(b * S + q0 + row) * HID + h * DH + c * 8;
    uint32_t so = row * (RS * 2) + c * 16;
    *(uint4*)(smem + AQ_H + so) = *(const uint4*)(Qh + g);
    *(uint4*)(smem + AQ_L + so) = *(const uint4*)(Ql + g);
  }
  __syncthreads();

  const int a_row = (l & 15);
  const int a_koff = ((l >> 4) & 1) * 16;
  const int b_row = (l & 7) + ((l >> 4) & 1) * 8;
  const int b_koff = ((l >> 3) & 1) * 16;
  const int v_row = (l & 7) + ((l >> 3) & 1) * 8;   // trans ldmatrix: key row
  const int v_col = ((l >> 4) & 1) * 16;            // dh byte offset (+8 dh)
  const int cb = (l & 3) * 2;

  // Q fragments live across the kv loop
  uint32_t qh[4][4], ql[4][4];
#pragma unroll
  for (int ks = 0; ks < 4; ks++) {
    uint32_t ra = (wid * 16 + a_row) * (RS * 2) + ks * 32 + a_koff;
    LDMX4(qh[ks][0], qh[ks][1], qh[ks][2], qh[ks][3], sb + AQ_H + ra);
    LDMX4(ql[ks][0], ql[ks][1], ql[ks][2], ql[ks][3], sb + AQ_L + ra);
  }

  float oacc[8][4] = {};
  float m0r = -1e30f, m1r = -1e30f, l0r = 0.f, l1r = 0.f;

  for (int kt = 0; kt < ntiles; kt++) {
    const int kbase = kt * 64;
    const uint32_t kb_h = sb + STG0 + (kt & 1) * STG_SZ;
    const uint32_t kb_l = kb_h + KV_COMP;
    const uint32_t vb_h = kb_h + 2 * KV_COMP;
    const uint32_t vb_l = kb_h + 3 * KV_COMP;

    CP_WAIT0();
    __syncthreads();   // tile kt visible; all warps done with stage (kt+1)&1
    if (kt + 1 < ntiles) {
      issue_tile((kt + 1) & 1, kbase + 64);
      CP_COMMIT();
    }

    // --- scores = Q K^T (bf16x3) ---
    float sc[8][4];
#pragma unroll
    for (int nt = 0; nt < 8; nt++)
#pragma unroll
      for (int c = 0; c < 4; c++) sc[nt][c] = 0.f;
#pragma unroll
    for (int ks = 0; ks < 4; ks++) {
      uint32_t khf[16], klf[16];
#pragma unroll
      for (int np = 0; np < 4; np++) {
        uint32_t rb = (np * 16 + b_row) * (RS * 2) + ks * 32 + b_koff;
        LDMX4(khf[np * 4 + 0], khf[np * 4 + 1], khf[np * 4 + 2],
              khf[np * 4 + 3], kb_h + rb);
        LDMX4(klf[np * 4 + 0], klf[np * 4 + 1], klf[np * 4 + 2],
              klf[np * 4 + 3], kb_l + rb);
      }
#pragma unroll
      for (int nt = 0; nt < 8; nt++) {
        float* c = sc[nt];
        mma_bf16(c[0], c[1], c[2], c[3], qh[ks][0], qh[ks][1], qh[ks][2],
                 qh[ks][3], khf[nt * 2], khf[nt * 2 + 1]);
        mma_bf16(c[0], c[1], c[2], c[3], qh[ks][0], qh[ks][1], qh[ks][2],
                 qh[ks][3], klf[nt * 2], klf[nt * 2 + 1]);
        mma_bf16(c[0], c[1], c[2], c[3], ql[ks][0], ql[ks][1], ql[ks][2],
                 ql[ks][3], khf[nt * 2], khf[nt * 2 + 1]);
      }
    }

    // --- scale + mask ---
#pragma unroll
    for (int nt = 0; nt < 8; nt++)
#pragma unroll
      for (int c = 0; c < 4; c++) sc[nt][c] *= 0.125f;
    if (kbase + 64 > vlen) {
#pragma unroll
      for (int nt = 0; nt < 8; nt++) {
        int k0 = kbase + nt * 8 + cb;
        if (k0 >= vlen) { sc[nt][0] = -1e30f; sc[nt][2] = -1e30f; }
        if (k0 + 1 >= vlen) { sc[nt][1] = -1e30f; sc[nt][3] = -1e30f; }
      }
    }

    // --- online softmax ---
    float rm0 = -1e30f, rm1 = -1e30f;
#pragma unroll
    for (int nt = 0; nt < 8; nt++) {
      rm0 = fmaxf(rm0, fmaxf(sc[nt][0], sc[nt][1]));
      rm1 = fmaxf(rm1, fmaxf(sc[nt][2], sc[nt][3]));
    }
    rm0 = fmaxf(rm0, __shfl_xor_sync(0xffffffffu, rm0, 1));
    rm0 = fmaxf(rm0, __shfl_xor_sync(0xffffffffu, rm0, 2));
    rm1 = fmaxf(rm1, __shfl_xor_sync(0xffffffffu, rm1, 1));
    rm1 = fmaxf(rm1, __shfl_xor_sync(0xffffffffu, rm1, 2));
    float mn0 = fmaxf(m0r, rm0), mn1 = fmaxf(m1r, rm1);
    float corr0 = __expf(m0r - mn0), corr1 = __expf(m1r - mn1);

    uint32_t ph[8][2], pl[8][2];
    float rs0 = 0.f, rs1 = 0.f;
#pragma unroll
    for (int nt = 0; nt < 8; nt++) {
      float p0 = __expf(sc[nt][0] - mn0);
      float p1 = __expf(sc[nt][1] - mn0);
      float p2 = __expf(sc[nt][2] - mn1);
      float p3 = __expf(sc[nt][3] - mn1);
      rs0 += p0 + p1;
      rs1 += p2 + p3;
      float h0 = __bfloat162float(__float2bfloat16(p0));
      float h1 = __bfloat162float(__float2bfloat16(p1));
      float h2 = __bfloat162float(__float2bfloat16(p2));
      float h3 = __bfloat162float(__float2bfloat16(p3));
      ph[nt][0] = pack_bf16(p0, p1);
      ph[nt][1] = pack_bf16(p2, p3);
      pl[nt][0] = pack_bf16(p0 - h0, p1 - h1);
      pl[nt][1] = pack_bf16(p2 - h2, p3 - h3);
    }
    rs0 += __shfl_xor_sync(0xffffffffu, rs0, 1);
    rs0 += __shfl_xor_sync(0xffffffffu, rs0, 2);
    rs1 += __shfl_xor_sync(0xffffffffu, rs1, 1);
    rs1 += __shfl_xor_sync(0xffffffffu, rs1, 2);
    l0r = l0r * corr0 + rs0;
    l1r = l1r * corr1 + rs1;
    m0r = mn0;
    m1r = mn1;
#pragma unroll
    for (int nt = 0; nt < 8; nt++) {
      oacc[nt][0] *= corr0;
      oacc[nt][1] *= corr0;
      oacc[nt][2] *= corr1;
      oacc[nt][3] *= corr1;
    }

    // --- oacc += P V : V fragments via ldmatrix.trans on row-major V ---
#pragma unroll
    for (int ks = 0; ks < 4; ks++) {
      uint32_t vhf[16], vlf[16];
#pragma unroll
      for (int np = 0; np < 4; np++) {
        uint32_t rv = (ks * 16 + v_row) * (RS * 2) + np * 32 + v_col;
        LDMX4T(vhf[np * 4 + 0], vhf[np * 4 + 1], vhf[np * 4 + 2],
               vhf[np * 4 + 3], vb_h + rv);
        LDMX4T(vlf[np * 4 + 0], vlf[np * 4 + 1], vlf[np * 4 + 2],
               vlf[np * 4 + 3], vb_l + rv);
      }
      uint32_t a0 = ph[2 * ks][0], a1 = ph[2 * ks][1];
      uint32_t a2 = ph[2 * ks + 1][0], a3 = ph[2 * ks + 1][1];
      uint32_t e0 = pl[2 * ks][0], e1 = pl[2 * ks][1];
      uint32_t e2 = pl[2 * ks + 1][0], e3 = pl[2 * ks + 1][1];
#pragma unroll
      for (int nt = 0; nt < 8; nt++) {
        float* c = oacc[nt];
        mma_bf16(c[0], c[1], c[2], c[3], a0, a1, a2, a3, vhf[nt * 2],
                 vhf[nt * 2 + 1]);
        mma_bf16(c[0], c[1], c[2], c[3], a0, a1, a2, a3, vlf[nt * 2],
                 vlf[nt * 2 + 1]);
        mma_bf16(c[0], c[1], c[2], c[3], e0, e1, e2, e3, vhf[nt * 2],
                 vhf[nt * 2 + 1]);
      }
    }
  }

  // --- epilogue: normalize, split to bf16 hi/lo, store ---
  float inv0 = 1.f / l0r, inv1 = 1.f / l1r;
  int r0 = q0 + wid * 16 + (l >> 2);
#pragma unroll
  for (int nt = 0; nt < 8; nt++) {
    int col = h * DH + nt * 8 + cb;
    float o0 = oacc[nt][0] * inv0, o1 = oacc[nt][1] * inv0;
    float o2 = oacc[nt][2] * inv1, o3 = oacc[nt][3] * inv1;
    float h0 = __bfloat162float(__float2bfloat16(o0));
    float h1 = __bfloat162float(__float2bfloat16(o1));
    float h2 = __bfloat162float(__float2bfloat16(o2));
    float h3 = __bfloat162float(__float2bfloat16(o3));
    size_t i0 = (size_t)(b * S + r0) * HID + col;
    size_t i1 = (size_t)(b * S + r0 + 8) * HID + col;
    *(uint32_t*)&Oh[i0] = pack_bf16(o0, o1);
    *(uint32_t*)&Ol[i0] = pack_bf16(o0 - h0, o1 - h1);
    *(uint32_t*)&Oh[i1] = pack_bf16(o2, o3);
    *(uint32_t*)&Ol[i1] = pack_bf16(o2 - h2, o3 - h3);
  }
}

// ---------------------------------------------------------------------------
extern "C" void kernel_launch(void* const* d_in, const int* in_sizes, int n_in,
                              void* d_out, int out_size) {
  const float* queries = (const float*)d_in[0];
  const float* keys    = (const float*)d_in[1];
  const float* values  = (const float*)d_in[2];
  const int*   vlens   = (const int*)d_in[3];
  const float* Wq      = (const float*)d_in[4];
  const float* Wk      = (const float*)d_in[5];
  const float* Wv      = (const float*)d_in[6];
  const float* Wo      = (const float*)d_in[7];
  float* out = (float*)d_out;

  __nv_bfloat16 *wh, *wl, *qh, *ql, *kh, *kl, *vh, *vl, *oh, *ol;
  cudaGetSymbolAddress((void**)&wh, g_wh);
  cudaGetSymbolAddress((void**)&wl, g_wl);
  cudaGetSymbolAddress((void**)&qh, g_qh);
  cudaGetSymbolAddress((void**)&ql, g_ql);
  cudaGetSymbolAddress((void**)&kh, g_kh);
  cudaGetSymbolAddress((void**)&kl, g_kl);
  cudaGetSymbolAddress((void**)&vh, g_vh);
  cudaGetSymbolAddress((void**)&vl, g_vl);
  cudaGetSymbolAddress((void**)&oh, g_oh);
  cudaGetSymbolAddress((void**)&ol, g_ol);

  cudaFuncSetAttribute(gemm_tc_hmma<true, true>,
                       cudaFuncAttributeMaxDynamicSharedMemorySize, GEMM_SMEM);
  cudaFuncSetAttribute(gemm_tc_hmma<false, false>,
                       cudaFuncAttributeMaxDynamicSharedMemorySize, GEMM_SMEM);
  cudaFuncSetAttribute(attn_hmma,
                       cudaFuncAttributeMaxDynamicSharedMemorySize, ATTN_SMEM);

  const int w_n4 = HID * HID / 4;
  dim3 gemm_grid(HID / 128, M / 128);  // (4, 64)

  // Q/K/V projections: A fp32 conversion fused; emit bf16 hi/lo
  split_kernel<<<w_n4 / 256, 256>>>(Wq, wh, wl, w_n4);
  gemm_tc_hmma<true, true><<<gemm_grid, 256, GEMM_SMEM>>>(
      queries, nullptr, nullptr, wh, wl, nullptr, qh, ql);
  split_kernel<<<w_n4 / 256, 256>>>(Wk, wh, wl, w_n4);
  gemm_tc_hmma<true, true><<<gemm_grid, 256, GEMM_SMEM>>>(
      keys, nullptr, nullptr, wh, wl, nullptr, kh, kl);
  split_kernel<<<w_n4 / 256, 256>>>(Wv, wh, wl, w_n4);
  gemm_tc_hmma<true, true><<<gemm_grid, 256, GEMM_SMEM>>>(
      values, nullptr, nullptr, wh, wl, nullptr, vh, vl);

  // attention
  attn_hmma<<<dim3(S / 128, NH, B), 256, ATTN_SMEM>>>(qh, ql, kh, kl, vh, vl,
                                                      vlens, oh, ol);

  // output projection (bf16 hi/lo A, fp32 out)
  split_kernel<<<w_n4 / 256, 256>>>(Wo, wh, wl, w_n4);
  gemm_tc_hmma<false, false><<<gemm_grid, 256, GEMM_SMEM>>>(
      nullptr, oh, ol, wh, wl, out, nullptr, nullptr);
}